// round 8
// baseline (speedup 1.0000x reference)
#include <cuda_runtime.h>
#include <cuda_bf16.h>

#define HD 256
#define BG 64
#define NPGC 4096
#define C0C 256
#define C1C 64
#define NTOT (BG*NPGC)
#define KSPLIT 16

__device__ unsigned g_A0P[(size_t)BG*C0C*NPGC];  // packed bf16 hi|lo<<16, [g][c][n]
__device__ unsigned g_W0P[C0C*HD];               // W0^T packed [c][k]
__device__ float g_f0[(size_t)BG*C0C*HD];
__device__ float g_A1[(size_t)BG*C0C*C1C];
__device__ float g_f1[(size_t)BG*C1C*HD];
__device__ float g_part[(size_t)KSPLIT*BG*HD];

__device__ __forceinline__ unsigned smem_u32(const void* p){
    unsigned a; asm("{ .reg .u64 t; cvta.to.shared.u64 t, %1; cvt.u32.u64 %0, t; }":"=r"(a):"l"(p)); return a;
}
__device__ __forceinline__ void cpa16(unsigned dst, const void* src){
    asm volatile("cp.async.cg.shared.global [%0], [%1], 16;" :: "r"(dst), "l"(src));
}
#define CP_COMMIT() asm volatile("cp.async.commit_group;" ::: "memory")
#define CP_WAIT0()  asm volatile("cp.async.wait_group 0;" ::: "memory")

__device__ __forceinline__ unsigned pack1(float v){
    __nv_bfloat16 h = __float2bfloat16(v);
    __nv_bfloat16 lo = __float2bfloat16(v - __bfloat162float(h));
    return (unsigned)__bfloat16_as_ushort(h) | ((unsigned)__bfloat16_as_ushort(lo)<<16);
}
__device__ __forceinline__ uint4 pack4(float4 v){
    return make_uint4(pack1(v.x), pack1(v.y), pack1(v.z), pack1(v.w));
}
__device__ __forceinline__ void mma16816(float* c, const unsigned* a, const unsigned* b){
    asm volatile("mma.sync.aligned.m16n8k16.row.col.f32.bf16.bf16.f32 "
        "{%0,%1,%2,%3}, {%4,%5,%6,%7}, {%8,%9}, {%0,%1,%2,%3};"
        : "+f"(c[0]),"+f"(c[1]),"+f"(c[2]),"+f"(c[3])
        : "r"(a[0]),"r"(a[1]),"r"(a[2]),"r"(a[3]), "r"(b[0]),"r"(b[1]));
}

// pack W0^T: g_W0P[c][k] = split(W0[k][c])
__global__ void kW(const float* __restrict__ W0){
    int i = blockIdx.x*256 + threadIdx.x;    // 65536
    int k = i>>8, c = i&255;
    g_W0P[c*HD + k] = pack1(W0[(size_t)k*C0C + c]);
}

// =========================================================================
// k1m: A0 = softmax(x@W0 + b0), HMMA split-bf16, 128 rows/CTA, 256 thr.
// =========================================================================
#define SX_STR 136
#define SW_STR 136
#define K1_SMEM (2048 + 128*SX_STR*4 + 256*SW_STR*4)   // 210944
__global__ __launch_bounds__(256,1) void k1m(const float* __restrict__ x,
                                             const float* __restrict__ b0){
    extern __shared__ __align__(16) unsigned sm[];
    float* sums = (float*)sm;                 // [128][2]
    float* b0s  = (float*)(sm + 256);         // [256]
    unsigned* sX = sm + 512;                  // [128][136]
    unsigned* sW = sm + 512 + 128*SX_STR;     // [256][136]
    unsigned* buf = sm + 512;                 // epilogue staging [256][132]
    const int tid = threadIdx.x, l = tid&31, wid = tid>>5;
    const int wm = wid&3, wn = wid>>2;
    const int row0 = blockIdx.x*128;

    b0s[tid] = b0[tid];
    float acc[2][16][4];
#pragma unroll
    for(int t=0;t<2;t++)
#pragma unroll
        for(int j=0;j<16;j++)
#pragma unroll
            for(int q=0;q<4;q++) acc[t][j][q]=0.f;

    for(int kc=0;kc<2;kc++){
#pragma unroll
        for(int i=0;i<16;i++){
            int idx = tid + i*256, r = idx>>5, q = idx&31;
            float4 v = *(const float4*)(x + (size_t)(row0+r)*HD + kc*128 + q*4);
            *(uint4*)(sX + r*SX_STR + q*4) = pack4(v);
        }
#pragma unroll
        for(int i=0;i<32;i++){
            int idx = tid + i*256, c = idx>>5, q = idx&31;
            *(uint4*)(sW + c*SW_STR + q*4) = *(const uint4*)(g_W0P + c*HD + kc*128 + q*4);
        }
        __syncthreads();
        for(int k16=0;k16<8;k16++){
            int kb = k16*16;
            unsigned ah[2][4], al[2][4];
#pragma unroll
            for(int t=0;t<2;t++){
                int ra = (wm*32 + t*16 + (l>>2))*SX_STR + kb + (l&3)*2;
                uint2 p0 = *(uint2*)(sX+ra),            p1 = *(uint2*)(sX+ra+8*SX_STR);
                uint2 p2 = *(uint2*)(sX+ra+8),          p3 = *(uint2*)(sX+ra+8*SX_STR+8);
                ah[t][0]=__byte_perm(p0.x,p0.y,0x5410); al[t][0]=__byte_perm(p0.x,p0.y,0x7632);
                ah[t][1]=__byte_perm(p1.x,p1.y,0x5410); al[t][1]=__byte_perm(p1.x,p1.y,0x7632);
                ah[t][2]=__byte_perm(p2.x,p2.y,0x5410); al[t][2]=__byte_perm(p2.x,p2.y,0x7632);
                ah[t][3]=__byte_perm(p3.x,p3.y,0x5410); al[t][3]=__byte_perm(p3.x,p3.y,0x7632);
            }
#pragma unroll
            for(int j=0;j<16;j++){
                int rb = (wn*128 + j*8 + (l>>2))*SW_STR + kb + (l&3)*2;
                uint2 q0 = *(uint2*)(sW+rb), q1 = *(uint2*)(sW+rb+8);
                unsigned bh[2], bl[2];
                bh[0]=__byte_perm(q0.x,q0.y,0x5410); bl[0]=__byte_perm(q0.x,q0.y,0x7632);
                bh[1]=__byte_perm(q1.x,q1.y,0x5410); bl[1]=__byte_perm(q1.x,q1.y,0x7632);
#pragma unroll
                for(int t=0;t<2;t++){
                    mma16816(acc[t][j], ah[t], bh);
                    mma16816(acc[t][j], ah[t], bl);
                    mma16816(acc[t][j], al[t], bh);
                }
            }
        }
        __syncthreads();
    }

    float rs[2][2] = {{0.f,0.f},{0.f,0.f}};
#pragma unroll
    for(int t=0;t<2;t++)
#pragma unroll
        for(int j=0;j<16;j++){
            int col = wn*128 + j*8 + (l&3)*2;
            float e0=__expf(acc[t][j][0]+b0s[col]),   e1=__expf(acc[t][j][1]+b0s[col+1]);
            float e2=__expf(acc[t][j][2]+b0s[col]),   e3=__expf(acc[t][j][3]+b0s[col+1]);
            acc[t][j][0]=e0; acc[t][j][1]=e1; acc[t][j][2]=e2; acc[t][j][3]=e3;
            rs[t][0]+=e0+e1; rs[t][1]+=e2+e3;
        }
#pragma unroll
    for(int t=0;t<2;t++)
#pragma unroll
        for(int h=0;h<2;h++){
            float s = rs[t][h];
            s += __shfl_xor_sync(~0u,s,1); s += __shfl_xor_sync(~0u,s,2);
            rs[t][h]=s;
        }
    if((l&3)==0){
#pragma unroll
        for(int t=0;t<2;t++)
#pragma unroll
            for(int h=0;h<2;h++)
                sums[(wm*32+t*16+(l>>2)+8*h)*2 + wn] = rs[t][h];
    }
    __syncthreads();
    float inv[2][2];
#pragma unroll
    for(int t=0;t<2;t++)
#pragma unroll
        for(int h=0;h<2;h++){
            int r = wm*32+t*16+(l>>2)+8*h;
            inv[t][h] = 1.0f/(sums[r*2]+sums[r*2+1]);
        }
#pragma unroll
    for(int t=0;t<2;t++)
#pragma unroll
        for(int j=0;j<16;j++){
            int col = wn*128 + j*8 + (l&3)*2;
            int r0 = wm*32 + t*16 + (l>>2), r1 = r0+8;
            buf[col*132 + r0]     = pack1(acc[t][j][0]*inv[t][0]);
            buf[(col+1)*132 + r0] = pack1(acc[t][j][1]*inv[t][0]);
            buf[col*132 + r1]     = pack1(acc[t][j][2]*inv[t][1]);
            buf[(col+1)*132 + r1] = pack1(acc[t][j][3]*inv[t][1]);
        }
    __syncthreads();
    const int g = row0>>12, nl0 = row0&4095;
#pragma unroll
    for(int cc=0;cc<32;cc++){
        int c = wid*32 + cc;
        uint4 v = *(uint4*)(buf + c*132 + l*4);
        *(uint4*)(g_A0P + ((size_t)g*C0C + c)*NPGC + nl0 + l*4) = v;
    }
}

// =========================================================================
// k2m: f0 = A0^T @ x per graph, cp.async 2-stage pipelined.
// grid(2 m-halves, 64 graphs). M=128, N=256, K=4096 in 64 chunks.
// =========================================================================
#define SA_STR 72
#define SB_STR 72
#define SF_STR 260
#define SA_CNT (128*SA_STR)          // u32 per A buffer
#define SF_BASE (2*SA_CNT)
#define SB_BASE (SF_BASE + 64*SF_STR)
#define K2_SMEM ((SB_BASE + 256*SB_STR)*4)    // 214016
__global__ __launch_bounds__(256,1) void k2m(const float* __restrict__ x){
    extern __shared__ __align__(16) unsigned sm[];
    float*   sF = (float*)(sm + SF_BASE);     // [64 n][260 h]
    unsigned* sB = sm + SB_BASE;              // [256 h][72 n]
    const unsigned sbase = smem_u32(sm);
    const int tid = threadIdx.x, l = tid&31, wid = tid>>5;
    const int wm = wid&3, wn = wid>>2;
    const int m0 = blockIdx.x*128, g = blockIdx.y;
    const unsigned* Ap = g_A0P + (size_t)g*C0C*NPGC;
    const float* xp = x + (size_t)g*NPGC*HD;

    float acc[2][16][4];
#pragma unroll
    for(int t=0;t<2;t++)
#pragma unroll
        for(int j=0;j<16;j++)
#pragma unroll
            for(int q=0;q<4;q++) acc[t][j][q]=0.f;

    // per-thread load coordinates
    // A chunk: 128 rows x 64 u32 -> 2048 uint4; 8 per thread.
    //   thread covers row ar = tid>>1, u32 offsets (tid&1)*32 + i*4, i<8
    const int ar = tid>>1, aq = (tid&1)*32;
    // F chunk: 64 rows x 256 f32 -> 4096 float4; 16 per thread.
    //   thread covers row fn = tid>>2, f32 offsets (tid&3)*64 + i*4, i<16
    const int fn = tid>>2, fq = (tid&3)*64;

    // prologue: issue chunk 0
#pragma unroll
    for(int i=0;i<8;i++)
        cpa16(sbase + (ar*SA_STR + aq + i*4)*4,
              Ap + (size_t)(m0+ar)*NPGC + 0*64 + aq + i*4);
#pragma unroll
    for(int i=0;i<16;i++)
        cpa16(sbase + (SF_BASE + fn*SF_STR + fq + i*4)*4,
              xp + (size_t)(0*64+fn)*HD + fq + i*4);
    CP_COMMIT();

    int buf = 0;
    for(int kc=0;kc<64;kc++){
        CP_WAIT0();
        __syncthreads();                       // sA[buf], sF ready; prev MMA done
        // transpose + split x: thread tid = h row
        {
            int h = tid;
#pragma unroll
            for(int n4=0;n4<16;n4++){
                unsigned p0 = pack1(sF[(n4*4+0)*SF_STR + h]);
                unsigned p1 = pack1(sF[(n4*4+1)*SF_STR + h]);
                unsigned p2 = pack1(sF[(n4*4+2)*SF_STR + h]);
                unsigned p3 = pack1(sF[(n4*4+3)*SF_STR + h]);
                *(uint4*)(sB + h*SB_STR + n4*4) = make_uint4(p0,p1,p2,p3);
            }
        }
        __syncthreads();                       // sB ready; sF consumed
        if (kc < 63){                          // prefetch next chunk during MMA
            int kn = kc+1;
#pragma unroll
            for(int i=0;i<8;i++)
                cpa16(sbase + ((buf^1)*SA_CNT + ar*SA_STR + aq + i*4)*4,
                      Ap + (size_t)(m0+ar)*NPGC + kn*64 + aq + i*4);
#pragma unroll
            for(int i=0;i<16;i++)
                cpa16(sbase + (SF_BASE + fn*SF_STR + fq + i*4)*4,
                      xp + (size_t)(kn*64+fn)*HD + fq + i*4);
            CP_COMMIT();
        }
        const unsigned* sA = sm + buf*SA_CNT;
        for(int k16=0;k16<4;k16++){
            int kb = k16*16;
            unsigned ah[2][4], al[2][4];
#pragma unroll
            for(int t=0;t<2;t++){
                int ra = (wm*32 + t*16 + (l>>2))*SA_STR + kb + (l&3)*2;
                uint2 p0 = *(uint2*)(sA+ra),   p1 = *(uint2*)(sA+ra+8*SA_STR);
                uint2 p2 = *(uint2*)(sA+ra+8), p3 = *(uint2*)(sA+ra+8*SA_STR+8);
                ah[t][0]=__byte_perm(p0.x,p0.y,0x5410); al[t][0]=__byte_perm(p0.x,p0.y,0x7632);
                ah[t][1]=__byte_perm(p1.x,p1.y,0x5410); al[t][1]=__byte_perm(p1.x,p1.y,0x7632);
                ah[t][2]=__byte_perm(p2.x,p2.y,0x5410); al[t][2]=__byte_perm(p2.x,p2.y,0x7632);
                ah[t][3]=__byte_perm(p3.x,p3.y,0x5410); al[t][3]=__byte_perm(p3.x,p3.y,0x7632);
            }
#pragma unroll
            for(int j=0;j<16;j++){
                int rb = (wn*128 + j*8 + (l>>2))*SB_STR + kb + (l&3)*2;
                uint2 q0 = *(uint2*)(sB+rb), q1 = *(uint2*)(sB+rb+8);
                unsigned bh[2], bl[2];
                bh[0]=__byte_perm(q0.x,q0.y,0x5410); bl[0]=__byte_perm(q0.x,q0.y,0x7632);
                bh[1]=__byte_perm(q1.x,q1.y,0x5410); bl[1]=__byte_perm(q1.x,q1.y,0x7632);
#pragma unroll
                for(int t=0;t<2;t++){
                    mma16816(acc[t][j], ah[t], bh);
                    mma16816(acc[t][j], ah[t], bl);
                    mma16816(acc[t][j], al[t], bh);
                }
            }
        }
        buf ^= 1;
    }
    float* f0p = g_f0 + ((size_t)g*C0C + m0)*HD;
#pragma unroll
    for(int t=0;t<2;t++)
#pragma unroll
        for(int j=0;j<16;j++){
            int col = wn*128 + j*8 + (l&3)*2;
            int r0 = wm*32 + t*16 + (l>>2);
            *(float2*)(f0p + (size_t)r0*HD + col)     = make_float2(acc[t][j][0],acc[t][j][1]);
            *(float2*)(f0p + (size_t)(r0+8)*HD + col) = make_float2(acc[t][j][2],acc[t][j][3]);
        }
}

// ---- k3: A1 = softmax(f0 @ W1 + b1). W1 staged in SMEM, 16 rows/block ----
#define K3_SMEM ((256*64 + 16*256)*4)   // 81920
__global__ __launch_bounds__(512) void k3n(const float* __restrict__ W1,
                                           const float* __restrict__ b1){
    extern __shared__ float s3[];
    float* sW = s3;                // [256][64]
    float* srow = s3 + 16384;      // [16][256]
    const int tid = threadIdx.x, l = tid&31, w = tid>>5;
#pragma unroll
    for(int i=0;i<8;i++){
        int idx = tid + i*512;     // 4096 float4
        *(float4*)(sW + idx*4) = *(const float4*)(W1 + idx*4);
    }
    const int row = blockIdx.x*16 + w;
    const float* xr = g_f0 + (size_t)row*HD;
    *(float4*)(srow + w*256 + l*8)     = *(const float4*)(xr + l*8);
    *(float4*)(srow + w*256 + l*8 + 4) = *(const float4*)(xr + l*8 + 4);
    __syncthreads();
    float a0=0.f, a1=0.f;
    const float* rw = srow + w*256;
#pragma unroll 8
    for(int k=0;k<HD;k++){
        float xv = rw[k];
        a0 = fmaf(xv, sW[k*64+l], a0);
        a1 = fmaf(xv, sW[k*64+l+32], a1);
    }
    a0 += __ldg(b1+l); a1 += __ldg(b1+l+32);
    float mx = fmaxf(a0,a1);
#pragma unroll
    for (int o=16;o;o>>=1) mx = fmaxf(mx, __shfl_xor_sync(~0u,mx,o));
    a0 = __expf(a0-mx); a1 = __expf(a1-mx);
    float s = a0+a1;
#pragma unroll
    for (int o=16;o;o>>=1) s += __shfl_xor_sync(~0u,s,o);
    float inv = 1.0f/s;
    g_A1[(size_t)row*C1C+l]    = a0*inv;
    g_A1[(size_t)row*C1C+l+32] = a1*inv;
}

// ---- k4: f1 = A1^T @ f0 per graph ----
__global__ __launch_bounds__(256) void k4_pool1(){
    __shared__ float As[32][64];
    __shared__ float Fs[32][128];
    const int g = blockIdx.y, n0 = blockIdx.x*128;
    const int tid = threadIdx.x, tx = tid&15, ty = tid>>4;
    float acc[4][8];
#pragma unroll
    for (int i=0;i<4;i++)
#pragma unroll
        for (int j=0;j<8;j++) acc[i][j]=0.f;
    const float* A1p = g_A1 + (size_t)g*C0C*C1C;
    const float* f0p = g_f0 + (size_t)g*C0C*HD;
    for (int kb=0;kb<C0C;kb+=32){
#pragma unroll
        for (int i=0;i<2;i++){
            int idx = tid + i*256;
            *(float4*)&As[idx>>4][(idx&15)*4] = *(const float4*)(A1p + (size_t)(kb+(idx>>4))*C1C + (idx&15)*4);
        }
#pragma unroll
        for (int i=0;i<4;i++){
            int idx = tid + i*256;
            *(float4*)&Fs[idx>>5][(idx&31)*4] = *(const float4*)(f0p + (size_t)(kb+(idx>>5))*HD + n0 + (idx&31)*4);
        }
        __syncthreads();
#pragma unroll
        for (int k=0;k<32;k++){
            float a[4], b[8];
            *(float4*)&a[0] = *(float4*)&As[k][ty*4];
            *(float4*)&b[0] = *(float4*)&Fs[k][tx*4];
            *(float4*)&b[4] = *(float4*)&Fs[k][tx*4+64];
#pragma unroll
            for (int i=0;i<4;i++)
#pragma unroll
                for (int j=0;j<8;j++) acc[i][j] = fmaf(a[i], b[j], acc[i][j]);
        }
        __syncthreads();
    }
    float* f1p = g_f1 + (size_t)g*C1C*HD;
#pragma unroll
    for (int ii=0;ii<4;ii++)
#pragma unroll
        for (int gn=0;gn<2;gn++)
            *(float4*)(f1p + (size_t)(ty*4+ii)*HD + n0 + tx*4 + gn*64) =
                make_float4(acc[ii][gn*4],acc[ii][gn*4+1],acc[ii][gn*4+2],acc[ii][gn*4+3]);
}

// ---- k5: K-split final GEMM partials ----
__global__ __launch_bounds__(256) void k5_final_part(const float* __restrict__ Wf){
    __shared__ float Fs[64][33];
    __shared__ float Ws[32][32];
    const int n0 = blockIdx.x*32, ks = blockIdx.y;
    const int tid = threadIdx.x, tx = tid&31, ty = tid>>5;
    float acc[8];
#pragma unroll
    for (int i=0;i<8;i++) acc[i]=0.f;
    const int kbeg = ks*1024;
    for (int kb=kbeg; kb<kbeg+1024; kb+=32){
#pragma unroll
        for (int i=0;i<2;i++){
            int idx = tid + i*256;
            int m = idx>>3, k = (idx&7)*4;
            float4 v = *(const float4*)(g_f1 + (size_t)m*(C1C*HD) + kb + k);
            Fs[m][k]=v.x; Fs[m][k+1]=v.y; Fs[m][k+2]=v.z; Fs[m][k+3]=v.w;
        }
        *(float4*)&Ws[tid>>3][(tid&7)*4] = *(const float4*)(Wf + (size_t)(kb+(tid>>3))*HD + n0 + (tid&7)*4);
        __syncthreads();
#pragma unroll
        for (int kk=0;kk<32;kk++){
            float b = Ws[kk][tx];
#pragma unroll
            for (int i=0;i<8;i++) acc[i] = fmaf(Fs[ty*8+i][kk], b, acc[i]);
        }
        __syncthreads();
    }
#pragma unroll
    for (int i=0;i<8;i++)
        g_part[(size_t)(ks*BG + ty*8+i)*HD + n0 + tx] = acc[i];
}

// ---- k6: reduce + bias + relu ----
__global__ __launch_bounds__(256) void k6_reduce(const float* __restrict__ bf, float* __restrict__ out){
    int idx = blockIdx.x*256 + threadIdx.x;
    float s = __ldg(bf + (idx&255));
#pragma unroll
    for (int ks=0;ks<KSPLIT;ks++) s += g_part[(size_t)ks*(BG*HD) + idx];
    out[idx] = fmaxf(s, 0.f);
}

extern "C" void kernel_launch(void* const* d_in, const int* in_sizes, int n_in,
                              void* d_out, int out_size){
    const float* x  = (const float*)d_in[0];
    const float* W0 = (const float*)d_in[3];
    const float* b0 = (const float*)d_in[4];
    const float* W1 = (const float*)d_in[5];
    const float* b1 = (const float*)d_in[6];
    const float* Wf = (const float*)d_in[7];
    const float* bf = (const float*)d_in[8];
    float* out = (float*)d_out;

    cudaFuncSetAttribute(k1m, cudaFuncAttributeMaxDynamicSharedMemorySize, K1_SMEM);
    cudaFuncSetAttribute(k2m, cudaFuncAttributeMaxDynamicSharedMemorySize, K2_SMEM);
    cudaFuncSetAttribute(k3n, cudaFuncAttributeMaxDynamicSharedMemorySize, K3_SMEM);

    kW<<<C0C*HD/256, 256>>>(W0);
    k1m<<<NTOT/128, 256, K1_SMEM>>>(x, b0);
    k2m<<<dim3(2, BG), 256, K2_SMEM>>>(x);
    k3n<<<BG*C0C/16, 512, K3_SMEM>>>(W1, b1);
    k4_pool1<<<dim3(2, BG), 256>>>();
    k5_final_part<<<dim3(8, KSPLIT), 256>>>(Wf);
    k6_reduce<<<BG*HD/256, 256>>>(bf, out);
}

// round 9
// speedup vs baseline: 1.1212x; 1.1212x over previous
#include <cuda_runtime.h>
#include <cuda_bf16.h>

#define HD 256
#define BG 64
#define NPGC 4096
#define C0C 256
#define C1C 64
#define NTOT (BG*NPGC)
#define KSPLIT 16

__device__ unsigned g_A0P[(size_t)BG*C0C*NPGC];  // packed bf16 hi|lo<<16, [g][c][n]
__device__ unsigned g_W0H[C0C*HD/2];             // W0^T hi pairs [c][128] u32
__device__ unsigned g_W0L[C0C*HD/2];             // W0^T lo pairs
__device__ float g_f0[(size_t)BG*C0C*HD];
__device__ float g_A1[(size_t)BG*C0C*C1C];
__device__ float g_f1[(size_t)BG*C1C*HD];
__device__ float g_part[(size_t)KSPLIT*BG*HD];

__device__ __forceinline__ unsigned pack1(float v){
    __nv_bfloat16 h = __float2bfloat16(v);
    __nv_bfloat16 lo = __float2bfloat16(v - __bfloat162float(h));
    return (unsigned)__bfloat16_as_ushort(h) | ((unsigned)__bfloat16_as_ushort(lo)<<16);
}
// split float pair -> (hi pair, lo pair)
__device__ __forceinline__ void split2(float a, float b, unsigned& hi, unsigned& lo){
    __nv_bfloat16 ha = __float2bfloat16(a), hb = __float2bfloat16(b);
    __nv_bfloat16 la = __float2bfloat16(a - __bfloat162float(ha));
    __nv_bfloat16 lb = __float2bfloat16(b - __bfloat162float(hb));
    hi = (unsigned)__bfloat16_as_ushort(ha) | ((unsigned)__bfloat16_as_ushort(hb)<<16);
    lo = (unsigned)__bfloat16_as_ushort(la) | ((unsigned)__bfloat16_as_ushort(lb)<<16);
}
__device__ __forceinline__ void mma16816(float* c, const unsigned* a, const unsigned* b){
    asm volatile("mma.sync.aligned.m16n8k16.row.col.f32.bf16.bf16.f32 "
        "{%0,%1,%2,%3}, {%4,%5,%6,%7}, {%8,%9}, {%0,%1,%2,%3};"
        : "+f"(c[0]),"+f"(c[1]),"+f"(c[2]),"+f"(c[3])
        : "r"(a[0]),"r"(a[1]),"r"(a[2]),"r"(a[3]), "r"(b[0]),"r"(b[1]));
}

// W0^T split into hi/lo pair arrays
__global__ void kW(const float* __restrict__ W0){
    int i = blockIdx.x*256 + threadIdx.x;    // 32768
    int c = i>>7, kp = i&127;
    unsigned hi, lo;
    split2(W0[(size_t)(2*kp)*C0C + c], W0[(size_t)(2*kp+1)*C0C + c], hi, lo);
    g_W0H[c*128+kp] = hi; g_W0L[c*128+kp] = lo;
}

// =========================================================================
// k1m: A0 = softmax(x@W0+b0). Separate hi/lo SMEM, no inner byte_perms.
// u32 offsets (from sm): XH=512, XL=9216, WH=17920, WL=35328. end 52736
// =========================================================================
#define K1_SMEM (52736*4)   // 210944
__global__ __launch_bounds__(256,1) void k1m(const float* __restrict__ x,
                                             const float* __restrict__ b0){
    extern __shared__ __align__(16) unsigned sm[];
    float* sums = (float*)sm;                 // [128][2]
    float* b0s  = (float*)(sm + 256);         // [256]
    unsigned* sXh = sm + 512;                 // [128][68]
    unsigned* sXl = sm + 9216;
    unsigned* sWh = sm + 17920;               // [256][68]
    unsigned* sWl = sm + 35328;
    unsigned* buf = sm + 512;                 // epilogue staging [256][132]
    const int tid = threadIdx.x, l = tid&31, wid = tid>>5;
    const int wm = wid&3, wn = wid>>2;
    const int row0 = blockIdx.x*128;

    b0s[tid] = b0[tid];
    float acc[2][16][4];
#pragma unroll
    for(int t=0;t<2;t++)
#pragma unroll
        for(int j=0;j<16;j++)
#pragma unroll
            for(int q=0;q<4;q++) acc[t][j][q]=0.f;

    for(int kc=0;kc<2;kc++){
        // x chunk [128 r][128 k] -> hi/lo pair arrays
#pragma unroll
        for(int i=0;i<16;i++){
            int idx = tid + i*256, r = idx>>5, q = idx&31;
            float4 v = *(const float4*)(x + (size_t)(row0+r)*HD + kc*128 + q*4);
            unsigned h0,l0,h1,l1;
            split2(v.x, v.y, h0, l0); split2(v.z, v.w, h1, l1);
            *(uint2*)(sXh + r*68 + q*2) = make_uint2(h0,h1);
            *(uint2*)(sXl + r*68 + q*2) = make_uint2(l0,l1);
        }
        // W chunk [256 c][64 pairs]
#pragma unroll
        for(int i=0;i<16;i++){
            int idx = tid + i*256, c = idx>>4, q = (idx&15)*4;
            *(uint4*)(sWh + c*68 + q) = *(const uint4*)(g_W0H + c*128 + kc*64 + q);
            *(uint4*)(sWl + c*68 + q) = *(const uint4*)(g_W0L + c*128 + kc*64 + q);
        }
        __syncthreads();
        for(int k16=0;k16<8;k16++){
            int kp = k16*8;
            unsigned ah[2][4], al[2][4];
#pragma unroll
            for(int t=0;t<2;t++){
                int ra = (wm*32 + t*16 + (l>>2))*68 + kp + (l&3);
                ah[t][0]=sXh[ra];       ah[t][1]=sXh[ra+8*68];
                ah[t][2]=sXh[ra+4];     ah[t][3]=sXh[ra+8*68+4];
                al[t][0]=sXl[ra];       al[t][1]=sXl[ra+8*68];
                al[t][2]=sXl[ra+4];     al[t][3]=sXl[ra+8*68+4];
            }
#pragma unroll
            for(int j=0;j<16;j++){
                int rb = (wn*128 + j*8 + (l>>2))*68 + kp + (l&3);
                unsigned bh[2], bl[2];
                bh[0]=sWh[rb]; bh[1]=sWh[rb+4];
                bl[0]=sWl[rb]; bl[1]=sWl[rb+4];
#pragma unroll
                for(int t=0;t<2;t++){
                    mma16816(acc[t][j], ah[t], bh);
                    mma16816(acc[t][j], ah[t], bl);
                    mma16816(acc[t][j], al[t], bh);
                }
            }
        }
        __syncthreads();
    }

    float rs[2][2] = {{0.f,0.f},{0.f,0.f}};
#pragma unroll
    for(int t=0;t<2;t++)
#pragma unroll
        for(int j=0;j<16;j++){
            int col = wn*128 + j*8 + (l&3)*2;
            float e0=__expf(acc[t][j][0]+b0s[col]),   e1=__expf(acc[t][j][1]+b0s[col+1]);
            float e2=__expf(acc[t][j][2]+b0s[col]),   e3=__expf(acc[t][j][3]+b0s[col+1]);
            acc[t][j][0]=e0; acc[t][j][1]=e1; acc[t][j][2]=e2; acc[t][j][3]=e3;
            rs[t][0]+=e0+e1; rs[t][1]+=e2+e3;
        }
#pragma unroll
    for(int t=0;t<2;t++)
#pragma unroll
        for(int h=0;h<2;h++){
            float s = rs[t][h];
            s += __shfl_xor_sync(~0u,s,1); s += __shfl_xor_sync(~0u,s,2);
            rs[t][h]=s;
        }
    if((l&3)==0){
#pragma unroll
        for(int t=0;t<2;t++)
#pragma unroll
            for(int h=0;h<2;h++)
                sums[(wm*32+t*16+(l>>2)+8*h)*2 + wn] = rs[t][h];
    }
    __syncthreads();
    float inv[2][2];
#pragma unroll
    for(int t=0;t<2;t++)
#pragma unroll
        for(int h=0;h<2;h++){
            int r = wm*32+t*16+(l>>2)+8*h;
            inv[t][h] = 1.0f/(sums[r*2]+sums[r*2+1]);
        }
#pragma unroll
    for(int t=0;t<2;t++)
#pragma unroll
        for(int j=0;j<16;j++){
            int col = wn*128 + j*8 + (l&3)*2;
            int r0 = wm*32 + t*16 + (l>>2), r1 = r0+8;
            buf[col*132 + r0]     = pack1(acc[t][j][0]*inv[t][0]);
            buf[(col+1)*132 + r0] = pack1(acc[t][j][1]*inv[t][0]);
            buf[col*132 + r1]     = pack1(acc[t][j][2]*inv[t][1]);
            buf[(col+1)*132 + r1] = pack1(acc[t][j][3]*inv[t][1]);
        }
    __syncthreads();
    const int g = row0>>12, nl0 = row0&4095;
#pragma unroll
    for(int cc=0;cc<32;cc++){
        int c = wid*32 + cc;
        uint4 v = *(uint4*)(buf + c*132 + l*4);
        *(uint4*)(g_A0P + ((size_t)g*C0C + c)*NPGC + nl0 + l*4) = v;
    }
}

// =========================================================================
// k2m: f0 = A0^T @ x per graph (synchronous R6 structure, separated hi/lo).
// u32 offsets: AH=0 [128][36], AL=4608, BH=9216 [256][36], BL=18432,
//              SF=27648 [64][260]f32. end 44288
// =========================================================================
#define K2_SMEM (44288*4)   // 177152
__global__ __launch_bounds__(256,1) void k2m(const float* __restrict__ x){
    extern __shared__ __align__(16) unsigned sm[];
    unsigned* sAh = sm;
    unsigned* sAl = sm + 4608;
    unsigned* sBh = sm + 9216;
    unsigned* sBl = sm + 18432;
    float*    sF  = (float*)(sm + 27648);     // [64 n][260 h]
    const int tid = threadIdx.x, l = tid&31, wid = tid>>5;
    const int wm = wid&3, wn = wid>>2;
    const int m0 = blockIdx.x*128, g = blockIdx.y;
    const unsigned* Ap = g_A0P + (size_t)g*C0C*NPGC;
    const float* xp = x + (size_t)g*NPGC*HD;

    float acc[2][16][4];
#pragma unroll
    for(int t=0;t<2;t++)
#pragma unroll
        for(int j=0;j<16;j++)
#pragma unroll
            for(int q=0;q<4;q++) acc[t][j][q]=0.f;

    for(int kc=0;kc<64;kc++){
        // A chunk [128 c][64 n] packed -> unpack once to hi/lo pair arrays
#pragma unroll
        for(int i=0;i<8;i++){
            int idx = tid + i*256, r = idx>>4, q = idx&15;
            uint4 w = *(const uint4*)(Ap + (size_t)(m0+r)*NPGC + kc*64 + q*4);
            unsigned h01 = __byte_perm(w.x,w.y,0x5410), h23 = __byte_perm(w.z,w.w,0x5410);
            unsigned l01 = __byte_perm(w.x,w.y,0x7632), l23 = __byte_perm(w.z,w.w,0x7632);
            *(uint2*)(sAh + r*36 + q*2) = make_uint2(h01,h23);
            *(uint2*)(sAl + r*36 + q*2) = make_uint2(l01,l23);
        }
        // x chunk [64 n][256 h] fp32
#pragma unroll
        for(int i=0;i<16;i++){
            int idx = tid + i*256, n = idx>>6, h4 = idx&63;
            *(float4*)(sF + n*260 + h4*4) = *(const float4*)(xp + (size_t)(kc*64+n)*HD + h4*4);
        }
        __syncthreads();
        // transpose + split: thread = h row; pairs along node dim
        {
            int h = tid;
#pragma unroll
            for(int n4=0;n4<16;n4++){
                float f0v = sF[(n4*4+0)*260 + h], f1v = sF[(n4*4+1)*260 + h];
                float f2v = sF[(n4*4+2)*260 + h], f3v = sF[(n4*4+3)*260 + h];
                unsigned h0,l0,h1,l1;
                split2(f0v, f1v, h0, l0); split2(f2v, f3v, h1, l1);
                *(uint2*)(sBh + h*36 + n4*2) = make_uint2(h0,h1);
                *(uint2*)(sBl + h*36 + n4*2) = make_uint2(l0,l1);
            }
        }
        __syncthreads();
        for(int k16=0;k16<4;k16++){
            int kp = k16*8;
            unsigned ah[2][4], al[2][4];
#pragma unroll
            for(int t=0;t<2;t++){
                int ra = (wm*32 + t*16 + (l>>2))*36 + kp + (l&3);
                ah[t][0]=sAh[ra];       ah[t][1]=sAh[ra+8*36];
                ah[t][2]=sAh[ra+4];     ah[t][3]=sAh[ra+8*36+4];
                al[t][0]=sAl[ra];       al[t][1]=sAl[ra+8*36];
                al[t][2]=sAl[ra+4];     al[t][3]=sAl[ra+8*36+4];
            }
#pragma unroll
            for(int j=0;j<16;j++){
                int rb = (wn*128 + j*8 + (l>>2))*36 + kp + (l&3);
                unsigned bh[2], bl[2];
                bh[0]=sBh[rb]; bh[1]=sBh[rb+4];
                bl[0]=sBl[rb]; bl[1]=sBl[rb+4];
#pragma unroll
                for(int t=0;t<2;t++){
                    mma16816(acc[t][j], ah[t], bh);
                    mma16816(acc[t][j], ah[t], bl);
                    mma16816(acc[t][j], al[t], bh);
                }
            }
        }
        __syncthreads();
    }
    float* f0p = g_f0 + ((size_t)g*C0C + m0)*HD;
#pragma unroll
    for(int t=0;t<2;t++)
#pragma unroll
        for(int j=0;j<16;j++){
            int col = wn*128 + j*8 + (l&3)*2;
            int r0 = wm*32 + t*16 + (l>>2);
            *(float2*)(f0p + (size_t)r0*HD + col)     = make_float2(acc[t][j][0],acc[t][j][1]);
            *(float2*)(f0p + (size_t)(r0+8)*HD + col) = make_float2(acc[t][j][2],acc[t][j][3]);
        }
}

// ---- k3: A1 = softmax(f0 @ W1 + b1). SMEM W1, float2 lanes ----
#define K3_SMEM ((256*64 + 16*256)*4)   // 81920
__global__ __launch_bounds__(512) void k3n(const float* __restrict__ W1,
                                           const float* __restrict__ b1){
    extern __shared__ float s3[];
    float* sW = s3;                // [256][64]
    float* srow = s3 + 16384;      // [16][256]
    const int tid = threadIdx.x, l = tid&31, w = tid>>5;
#pragma unroll
    for(int i=0;i<8;i++){
        int idx = tid + i*512;
        *(float4*)(sW + idx*4) = *(const float4*)(W1 + idx*4);
    }
    const int row = blockIdx.x*16 + w;
    const float* xr = g_f0 + (size_t)row*HD;
    *(float4*)(srow + w*256 + l*8)     = *(const float4*)(xr + l*8);
    *(float4*)(srow + w*256 + l*8 + 4) = *(const float4*)(xr + l*8 + 4);
    __syncthreads();
    float a0=0.f, a1=0.f;
    const float* rw = srow + w*256;
#pragma unroll 8
    for(int k=0;k<HD;k++){
        float xv = rw[k];
        float2 wv = *(float2*)(sW + k*64 + 2*l);
        a0 = fmaf(xv, wv.x, a0);
        a1 = fmaf(xv, wv.y, a1);
    }
    float2 bb = *(const float2*)(b1 + 2*l);
    a0 += bb.x; a1 += bb.y;
    float mx = fmaxf(a0,a1);
#pragma unroll
    for (int o=16;o;o>>=1) mx = fmaxf(mx, __shfl_xor_sync(~0u,mx,o));
    a0 = __expf(a0-mx); a1 = __expf(a1-mx);
    float s = a0+a1;
#pragma unroll
    for (int o=16;o;o>>=1) s += __shfl_xor_sync(~0u,s,o);
    float inv = 1.0f/s;
    *(float2*)(g_A1 + (size_t)row*C1C + 2*l) = make_float2(a0*inv, a1*inv);
}

// ---- k4: f1 = A1^T @ f0 per graph ----
__global__ __launch_bounds__(256) void k4_pool1(){
    __shared__ float As[32][64];
    __shared__ float Fs[32][128];
    const int g = blockIdx.y, n0 = blockIdx.x*128;
    const int tid = threadIdx.x, tx = tid&15, ty = tid>>4;
    float acc[4][8];
#pragma unroll
    for (int i=0;i<4;i++)
#pragma unroll
        for (int j=0;j<8;j++) acc[i][j]=0.f;
    const float* A1p = g_A1 + (size_t)g*C0C*C1C;
    const float* f0p = g_f0 + (size_t)g*C0C*HD;
    for (int kb=0;kb<C0C;kb+=32){
#pragma unroll
        for (int i=0;i<2;i++){
            int idx = tid + i*256;
            *(float4*)&As[idx>>4][(idx&15)*4] = *(const float4*)(A1p + (size_t)(kb+(idx>>4))*C1C + (idx&15)*4);
        }
#pragma unroll
        for (int i=0;i<4;i++){
            int idx = tid + i*256;
            *(float4*)&Fs[idx>>5][(idx&31)*4] = *(const float4*)(f0p + (size_t)(kb+(idx>>5))*HD + n0 + (idx&31)*4);
        }
        __syncthreads();
#pragma unroll
        for (int k=0;k<32;k++){
            float a[4], b[8];
            *(float4*)&a[0] = *(float4*)&As[k][ty*4];
            *(float4*)&b[0] = *(float4*)&Fs[k][tx*4];
            *(float4*)&b[4] = *(float4*)&Fs[k][tx*4+64];
#pragma unroll
            for (int i=0;i<4;i++)
#pragma unroll
                for (int j=0;j<8;j++) acc[i][j] = fmaf(a[i], b[j], acc[i][j]);
        }
        __syncthreads();
    }
    float* f1p = g_f1 + (size_t)g*C1C*HD;
#pragma unroll
    for (int ii=0;ii<4;ii++)
#pragma unroll
        for (int gn=0;gn<2;gn++)
            *(float4*)(f1p + (size_t)(ty*4+ii)*HD + n0 + tx*4 + gn*64) =
                make_float4(acc[ii][gn*4],acc[ii][gn*4+1],acc[ii][gn*4+2],acc[ii][gn*4+3]);
}

// ---- k5: K-split final GEMM partials ----
__global__ __launch_bounds__(256) void k5_final_part(const float* __restrict__ Wf){
    __shared__ float Fs[64][33];
    __shared__ float Ws[32][32];
    const int n0 = blockIdx.x*32, ks = blockIdx.y;
    const int tid = threadIdx.x, tx = tid&31, ty = tid>>5;
    float acc[8];
#pragma unroll
    for (int i=0;i<8;i++) acc[i]=0.f;
    const int kbeg = ks*1024;
    for (int kb=kbeg; kb<kbeg+1024; kb+=32){
#pragma unroll
        for (int i=0;i<2;i++){
            int idx = tid + i*256;
            int m = idx>>3, k = (idx&7)*4;
            float4 v = *(const float4*)(g_f1 + (size_t)m*(C1C*HD) + kb + k);
            Fs[m][k]=v.x; Fs[m][k+1]=v.y; Fs[m][k+2]=v.z; Fs[m][k+3]=v.w;
        }
        *(float4*)&Ws[tid>>3][(tid&7)*4] = *(const float4*)(Wf + (size_t)(kb+(tid>>3))*HD + n0 + (tid&7)*4);
        __syncthreads();
#pragma unroll
        for (int kk=0;kk<32;kk++){
            float b = Ws[kk][tx];
#pragma unroll
            for (int i=0;i<8;i++) acc[i] = fmaf(Fs[ty*8+i][kk], b, acc[i]);
        }
        __syncthreads();
    }
#pragma unroll
    for (int i=0;i<8;i++)
        g_part[(size_t)(ks*BG + ty*8+i)*HD + n0 + tx] = acc[i];
}

// ---- k6: reduce + bias + relu ----
__global__ __launch_bounds__(256) void k6_reduce(const float* __restrict__ bf, float* __restrict__ out){
    int idx = blockIdx.x*256 + threadIdx.x;
    float s = __ldg(bf + (idx&255));
#pragma unroll
    for (int ks=0;ks<KSPLIT;ks++) s += g_part[(size_t)ks*(BG*HD) + idx];
    out[idx] = fmaxf(s, 0.f);
}

extern "C" void kernel_launch(void* const* d_in, const int* in_sizes, int n_in,
                              void* d_out, int out_size){
    const float* x  = (const float*)d_in[0];
    const float* W0 = (const float*)d_in[3];
    const float* b0 = (const float*)d_in[4];
    const float* W1 = (const float*)d_in[5];
    const float* b1 = (const float*)d_in[6];
    const float* Wf = (const float*)d_in[7];
    const float* bf = (const float*)d_in[8];
    float* out = (float*)d_out;

    cudaFuncSetAttribute(k1m, cudaFuncAttributeMaxDynamicSharedMemorySize, K1_SMEM);
    cudaFuncSetAttribute(k2m, cudaFuncAttributeMaxDynamicSharedMemorySize, K2_SMEM);
    cudaFuncSetAttribute(k3n, cudaFuncAttributeMaxDynamicSharedMemorySize, K3_SMEM);

    kW<<<C0C*HD/2/256, 256>>>(W0);
    k1m<<<NTOT/128, 256, K1_SMEM>>>(x, b0);
    k2m<<<dim3(2, BG), 256, K2_SMEM>>>(x);
    k3n<<<BG*C0C/16, 512, K3_SMEM>>>(W1, b1);
    k4_pool1<<<dim3(2, BG), 256>>>();
    k5_final_part<<<dim3(8, KSPLIT), 256>>>(Wf);
    k6_reduce<<<BG*HD/256, 256>>>(bf, out);
}